// round 2
// baseline (speedup 1.0000x reference)
#include <cuda_runtime.h>
#include <math.h>

#define NPTS 32768
#define KK 32
#define DD 64
#define PACKED 2176          // triangle rows padded to float4 boundaries
#define LOG_2PI 1.8378770664093453f

// ---------------- device scratch (no allocations allowed) ----------------
__device__ float g_C[KK][DD * DD];     // Sigma, then Cholesky factor (lower)
__device__ float g_W[KK][DD * DD];     // W = C^{-1} (lower triangular)
__device__ float g_Bp[KK][PACKED];     // packed -0.5*Sinv (offdiag doubled), rows 4-aligned
__device__ float g_bv[KK][DD];         // b_k = Sinv * mu_k
__device__ float g_ck[KK];             // logw_k - 0.5*(D*log2pi + logdet + mu.b)
__device__ float g_logdet[KK];
__device__ float g_c2[KK];
__device__ float g_loglik[NPTS];

// ---------------- Kernel 1: Sigma = tril(L) tril(L)^T + I ----------------
__global__ void sigma_kernel(const float* __restrict__ L) {
    int k = blockIdx.x;
    __shared__ float sL[DD * DD];
    const float4* src = (const float4*)(L + (size_t)k * DD * DD);
    float4* dst = (float4*)sL;
    for (int i = threadIdx.x; i < DD * DD / 4; i += blockDim.x) dst[i] = src[i];
    __syncthreads();
    for (int idx = threadIdx.x; idx < DD * DD; idx += blockDim.x) {
        int d = idx >> 6, e = idx & 63;
        int mm = min(d, e);
        float s = 0.f;
        for (int m = 0; m <= mm; m++) s = fmaf(sL[d * DD + m], sL[e * DD + m], s);
        if (d == e) s += 1.0f;
        g_C[k][idx] = s;
    }
}

// ---------------- Kernel 2: in-place Cholesky (64 threads/block) ----------------
__global__ void chol_kernel() {
    int k = blockIdx.x, tid = threadIdx.x;
    __shared__ float A[DD][DD + 1];
    for (int c = 0; c < DD; c++) A[tid][c] = g_C[k][tid * DD + c];
    __syncthreads();
    for (int j = 0; j < DD; j++) {
        float ajj = A[j][j];
        __syncthreads();
        float djj = sqrtf(ajj);
        float inv = 1.0f / djj;
        if (tid == j) A[j][j] = djj;
        else if (tid > j) A[tid][j] *= inv;
        __syncthreads();
        if (tid > j) {
            float l = A[tid][j];
            for (int c = j + 1; c <= tid; c++) A[tid][c] = fmaf(-l, A[c][j], A[tid][c]);
        }
        __syncthreads();
    }
    for (int c = 0; c < DD; c++) g_C[k][tid * DD + c] = (c <= tid) ? A[tid][c] : 0.0f;
    if (tid == 0) {
        float s = 0.f;
        for (int d = 0; d < DD; d++) s += logf(A[d][d]);
        g_logdet[k] = 2.0f * s;
    }
}

// ---------------- Kernel 3: W = C^{-1}, one column per thread ----------------
__global__ void trinv_kernel() {
    int k = blockIdx.x, j = threadIdx.x;
    __shared__ float C[DD][DD + 1];
    __shared__ float Y[DD][DD + 1];   // Y[i][j] = column j of W (per-thread column)
    for (int c = 0; c < DD; c++) C[j][c] = g_C[k][j * DD + c];
    __syncthreads();
    Y[j][j] = 1.0f / C[j][j];
    for (int i = j + 1; i < DD; i++) {
        float s = 0.f;
        for (int m = j; m < i; m++) s = fmaf(C[i][m], Y[m][j], s);
        Y[i][j] = -s / C[i][i];
    }
    __syncthreads();
    for (int i = 0; i < DD; i++) g_W[k][i * DD + j] = (i >= j) ? Y[i][j] : 0.f;
}

// ---------------- Kernel 4: b = W^T(W mu), c2 = mu.b, packed -0.5*Sinv ----------------
__global__ void pack_kernel(const float* __restrict__ mu) {
    int k = blockIdx.x, tid = threadIdx.x;
    __shared__ float W[DD][DD];
    __shared__ float u[DD];
    __shared__ float bsh[DD];
    for (int i = tid; i < DD * DD; i += 256) W[i >> 6][i & 63] = g_W[k][i];
    __syncthreads();
    if (tid < DD) {
        float s = 0.f;
        for (int e = 0; e <= tid; e++) s = fmaf(W[tid][e], mu[k * DD + e], s);
        u[tid] = s;
    }
    __syncthreads();
    if (tid < DD) {
        float s = 0.f;
        for (int m = tid; m < DD; m++) s = fmaf(W[m][tid], u[m], s);
        bsh[tid] = s;
        g_bv[k][tid] = s;
    }
    __syncthreads();
    if (tid == 0) {
        float c2 = 0.f;
        for (int d = 0; d < DD; d++) c2 = fmaf(mu[k * DD + d], bsh[d], c2);
        g_c2[k] = c2;
    }
    // packed B': row d, entries e<=d; Sinv[d][e] = sum_{m>=d} W[m][d]*W[m][e]
    int d = tid >> 2;
    int lane = tid & 3;
    int q = d >> 2, r = d & 3;
    int off = 4 * (q + 1) * (2 * q + r);
    int plen = 4 * (q + 1);
    for (int e = lane; e < plen; e += 4) {
        float val = 0.f;
        if (e <= d) {
            float s = 0.f;
            for (int m = d; m < DD; m++) s = fmaf(W[m][d], W[m][e], s);
            val = (e == d) ? -0.5f * s : -s;   // -0.5 folded, offdiag doubled
        }
        g_Bp[k][off + e] = val;
    }
}

// ---------------- Kernel 5: log_softmax(weights) + constants ----------------
__global__ void finalize_kernel(const float* __restrict__ w) {
    int t = threadIdx.x;
    float wv = w[t];
    float m = wv;
    for (int o = 16; o; o >>= 1) m = fmaxf(m, __shfl_xor_sync(0xffffffffu, m, o));
    float s = expf(wv - m);
    for (int o = 16; o; o >>= 1) s += __shfl_xor_sync(0xffffffffu, s, o);
    float logw = wv - (m + logf(s));
    g_ck[t] = logw - 0.5f * (DD * LOG_2PI + g_logdet[t] + g_c2[t]);
}

// ---------------- Main kernel: per-point log-mixture via packed quadratic ----------------
// block = (64 points, 2 k-halves); x resident in registers across all k
__global__ void __launch_bounds__(128) main_kernel(const float* __restrict__ X) {
    __shared__ float sB[2][PACKED];
    __shared__ float sb[2][DD];
    __shared__ float sc[2];
    __shared__ float smx[2][64];
    __shared__ float ssm[2][64];
    int tx = threadIdx.x, ty = threadIdx.y;
    int n = blockIdx.x * 64 + tx;

    float x[DD];
    const float4* xp = (const float4*)(X + (size_t)n * DD);
#pragma unroll
    for (int i = 0; i < 16; i++) {
        float4 v = xp[i];
        x[4 * i] = v.x; x[4 * i + 1] = v.y; x[4 * i + 2] = v.z; x[4 * i + 3] = v.w;
    }

    float mx = -INFINITY, sm = 0.f;
#pragma unroll 1
    for (int i = 0; i < 16; i++) {
        int k = ty * 16 + i;
        __syncthreads();
        {
            const float4* src = (const float4*)g_Bp[k];
            float4* dst = (float4*)sB[ty];
            for (int j = tx; j < PACKED / 4; j += 64) dst[j] = src[j];
            if (tx < 16) ((float4*)sb[ty])[tx] = ((const float4*)g_bv[k])[tx];
            if (tx == 0) sc[ty] = g_ck[k];
        }
        __syncthreads();

        const float4* B4 = (const float4*)sB[ty];
        const float* bb = sb[ty];
        float acc = sc[ty];
        int off4 = 0;
#pragma unroll
        for (int d = 0; d < DD; d++) {
            int g = (d >> 2) + 1;
            float t0 = bb[d], t1 = 0.f;
#pragma unroll
            for (int j = 0; j < g; j++) {
                float4 v = B4[off4 + j];
                if (j & 1) {
                    t1 = fmaf(v.x, x[4 * j], t1);
                    t1 = fmaf(v.y, x[4 * j + 1], t1);
                    t1 = fmaf(v.z, x[4 * j + 2], t1);
                    t1 = fmaf(v.w, x[4 * j + 3], t1);
                } else {
                    t0 = fmaf(v.x, x[4 * j], t0);
                    t0 = fmaf(v.y, x[4 * j + 1], t0);
                    t0 = fmaf(v.z, x[4 * j + 2], t0);
                    t0 = fmaf(v.w, x[4 * j + 3], t0);
                }
            }
            off4 += g;
            acc = fmaf(x[d], t0 + t1, acc);   // logp accumulates: ck + b.x - 0.5 x^T Sinv x
        }
        // online logsumexp over this thread's k values
        if (acc > mx) {
            sm = fmaf(sm, expf(mx - acc), 1.0f);
            mx = acc;
        } else {
            sm += expf(acc - mx);
        }
    }
    smx[ty][tx] = mx;
    ssm[ty][tx] = sm;
    __syncthreads();
    if (ty == 0) {
        float m0 = smx[0][tx], m1 = smx[1][tx];
        float s0 = ssm[0][tx], s1 = ssm[1][tx];
        float M = fmaxf(m0, m1);
        float S = s0 * expf(m0 - M) + s1 * expf(m1 - M);
        g_loglik[n] = M + logf(S);
    }
}

// ---------------- Final reduce: -logsumexp over N ----------------
__global__ void reduce_kernel(float* __restrict__ out) {
    __shared__ float red[32];
    int tid = threadIdx.x;
    float m = -INFINITY;
    for (int i = tid; i < NPTS; i += 1024) m = fmaxf(m, g_loglik[i]);
    for (int o = 16; o; o >>= 1) m = fmaxf(m, __shfl_xor_sync(0xffffffffu, m, o));
    if ((tid & 31) == 0) red[tid >> 5] = m;
    __syncthreads();
    if (tid < 32) {
        float v = red[tid];
        for (int o = 16; o; o >>= 1) v = fmaxf(v, __shfl_xor_sync(0xffffffffu, v, o));
        if (tid == 0) red[0] = v;
    }
    __syncthreads();
    float M = red[0];
    __syncthreads();
    float s = 0.f;
    for (int i = tid; i < NPTS; i += 1024) s += expf(g_loglik[i] - M);
    for (int o = 16; o; o >>= 1) s += __shfl_xor_sync(0xffffffffu, s, o);
    if ((tid & 31) == 0) red[tid >> 5] = s;
    __syncthreads();
    if (tid == 0) {
        float t = 0.f;
        for (int i = 0; i < 32; i++) t += red[i];
        out[0] = -(M + logf(t));
    }
}

// ---------------- launch ----------------
extern "C" void kernel_launch(void* const* d_in, const int* in_sizes, int n_in,
                              void* d_out, int out_size) {
    const float* X  = (const float*)d_in[0];
    const float* mu = (const float*)d_in[1];
    const float* L  = (const float*)d_in[2];
    const float* w  = (const float*)d_in[3];
    float* out = (float*)d_out;

    sigma_kernel<<<KK, 256>>>(L);
    chol_kernel<<<KK, 64>>>();
    trinv_kernel<<<KK, 64>>>();
    pack_kernel<<<KK, 256>>>(mu);
    finalize_kernel<<<1, 32>>>(w);

    dim3 blk(64, 2);
    main_kernel<<<NPTS / 64, blk>>>(X);
    reduce_kernel<<<1, 1024>>>(out);
}

// round 3
// speedup vs baseline: 1.9688x; 1.9688x over previous
#include <cuda_runtime.h>
#include <math.h>

#define NPTS 32768
#define KK 32
#define DD 64
#define PACKED 2176                 // triangle rows padded to float4 boundaries (floats)
#define LOG_2PI 1.8378770664093453f

// ---------------- packed per-component parameter block ----------------
// B: packed -0.5*Sinv lower triangle (offdiag doubled), rows padded to float4.
// b: Sinv*mu as 32 float-pairs. ck: logw - 0.5*(D log2pi + logdet + mu.b).
struct KPack {
    ulonglong2 B[PACKED / 4];       // 8704 B
    unsigned long long b[DD / 2];   // 256 B
    float ck;
    float pad[3];                   // -> 8976 B total (16-multiple)
};
__device__ KPack g_pk[KK];
__device__ float g_loglik[NPTS];

// ---------------- packed f32x2 helpers (sm_103a) ----------------
#define FMA2(acc, a, b) asm("fma.rn.f32x2 %0, %1, %2, %0;" : "+l"(acc) : "l"(a), "l"(b))
#define ADD2(d, a, b)   asm("add.rn.f32x2 %0, %1, %2;" : "=l"(d) : "l"(a), "l"(b))
#define UNPK(lo, hi, v) asm("mov.b64 {%0, %1}, %2;" : "=f"(lo), "=f"(hi) : "l"(v))
#define PK(u, a, b)     asm("mov.b64 %0, {%1, %2};" : "=l"(u) : "f"(a), "f"(b))

// ---------------- mbarrier + bulk-copy helpers ----------------
__device__ __forceinline__ unsigned smem_u32(const void* p) {
    unsigned r;
    asm("{ .reg .u64 t; cvta.to.shared.u64 t, %1; cvt.u32.u64 %0, t; }" : "=r"(r) : "l"(p));
    return r;
}
#define MBAR_INIT(addr, cnt) \
    asm volatile("mbarrier.init.shared.b64 [%0], %1;" :: "r"(addr), "r"(cnt) : "memory")
#define MBAR_EXPECT_TX(addr, bytes) \
    asm volatile("mbarrier.arrive.expect_tx.shared.b64 _, [%0], %1;" :: "r"(addr), "r"(bytes) : "memory")
#define MBAR_WAIT(addr, parity) \
    asm volatile("{\n\t.reg .pred P;\n\tWL_%=:\n\t" \
        "mbarrier.try_wait.parity.acquire.cta.shared::cta.b64 P, [%0], %1, 0x989680;\n\t" \
        "@P bra.uni WD_%=;\n\tbra.uni WL_%=;\n\tWD_%=:\n\t}" \
        :: "r"(addr), "r"(parity) : "memory")
#define BULK_CP(dst, src, bytes, bar) \
    asm volatile("cp.async.bulk.shared::cluster.global.mbarrier::complete_tx::bytes [%0], [%1], %2, [%3];" \
        :: "r"(dst), "l"(src), "r"(bytes), "r"(bar) : "memory")

// ---------------- fused setup: Sigma -> Cholesky -> W=C^{-1} -> pack ----------------
__global__ void __launch_bounds__(256) setup_kernel(const float* __restrict__ L,
                                                    const float* __restrict__ mu,
                                                    const float* __restrict__ w) {
    int k = blockIdx.x, tid = threadIdx.x;
    __shared__ float sL[DD][DD];
    __shared__ float A[DD][DD + 1];     // Sigma, then Cholesky lower factor
    __shared__ float Wm[DD][DD + 1];    // W = C^{-1} (lower)
    __shared__ float invd[DD];
    __shared__ float u[DD], bsh[DD];
    __shared__ float sc2, slogdet;

    // load L (row-major [64][64])
    const float4* src = (const float4*)(L + (size_t)k * DD * DD);
    for (int i = tid; i < DD * DD / 4; i += 256) {
        float4 v = src[i];
        int r = i >> 4, c = (i & 15) * 4;
        sL[r][c] = v.x; sL[r][c + 1] = v.y; sL[r][c + 2] = v.z; sL[r][c + 3] = v.w;
    }
    __syncthreads();

    // Sigma = tril(L) tril(L)^T + I
    for (int idx = tid; idx < DD * DD; idx += 256) {
        int d = idx >> 6, e = idx & 63;
        int mm = min(d, e);
        float s = (d == e) ? 1.0f : 0.0f;
        for (int m = 0; m <= mm; m++) s = fmaf(sL[d][m], sL[e][m], s);
        A[d][e] = s;
    }
    __syncthreads();

    // Cholesky (lower), parallel update: 4 threads per row
    int ri = tid & 63, l4 = tid >> 6;
    for (int j = 0; j < DD; j++) {
        float djj = sqrtf(A[j][j]);
        float inv = 1.0f / djj;
        if (l4 == 0 && ri > j) A[ri][j] *= inv;
        __syncthreads();
        if (ri > j) {
            float lv = A[ri][j];
            for (int c = j + 1 + l4; c <= ri; c += 4) A[ri][c] = fmaf(-lv, A[c][j], A[ri][c]);
        }
        if (l4 == 0 && ri == j) A[j][j] = djj;
        __syncthreads();
    }
    // logdet + reciprocal diag
    if (tid < DD) { u[tid] = logf(A[tid][tid]); invd[tid] = 1.0f / A[tid][tid]; }
    __syncthreads();
    if (tid == 0) {
        float s = 0.f;
        for (int d = 0; d < DD; d++) s += u[d];
        slogdet = 2.0f * s;
    }
    __syncthreads();

    // W = C^{-1}: forward substitution, one thread per column
    if (tid < DD) {
        int j = tid;
        Wm[j][j] = invd[j];
        for (int i = j + 1; i < DD; i++) {
            float s = 0.f;
            for (int m = j; m < i; m++) s = fmaf(A[i][m], Wm[m][j], s);
            Wm[i][j] = -s * invd[i];
        }
    }
    __syncthreads();

    // pack B' rows: Sinv[d][e] = sum_{m>=d} W[m][d] W[m][e] (e<=d); -0.5 folded, offdiag doubled
    {
        int d = tid >> 2, lane = tid & 3;
        int q = d >> 2, r = d & 3;
        int off = 4 * (q + 1) * (2 * q + r);
        int plen = 4 * (q + 1);
        float* Bf = (float*)g_pk[k].B;
        for (int e = lane; e < plen; e += 4) {
            float val = 0.f;
            if (e <= d) {
                float s = 0.f;
                for (int m = d; m < DD; m++) s = fmaf(Wm[m][d], Wm[m][e], s);
                val = (e == d) ? -0.5f * s : -s;
            }
            Bf[off + e] = val;
        }
    }

    // b = W^T (W mu), c2 = mu.b
    if (tid < DD) {
        float s = 0.f;
        for (int e = 0; e <= tid; e++) s = fmaf(Wm[tid][e], mu[k * DD + e], s);
        u[tid] = s;
    }
    __syncthreads();
    if (tid < DD) {
        float s = 0.f;
        for (int m = tid; m < DD; m++) s = fmaf(Wm[m][tid], u[m], s);
        bsh[tid] = s;
        ((float*)g_pk[k].b)[tid] = s;
    }
    __syncthreads();
    if (tid == 0) {
        float c2 = 0.f;
        for (int d = 0; d < DD; d++) c2 = fmaf(mu[k * DD + d], bsh[d], c2);
        sc2 = c2;
    }
    __syncthreads();

    // ck = log_softmax(w)[k] - 0.5*(D log2pi + logdet + c2)
    if (tid < KK) {
        float wv = w[tid];
        float m = wv;
        for (int o = 16; o; o >>= 1) m = fmaxf(m, __shfl_xor_sync(0xffffffffu, m, o));
        float s = expf(wv - m);
        for (int o = 16; o; o >>= 1) s += __shfl_xor_sync(0xffffffffu, s, o);
        float logw = wv - (m + logf(s));
        float lk = __shfl_sync(0xffffffffu, logw, k);
        if (tid == 0) g_pk[k].ck = lk - 0.5f * (DD * LOG_2PI + slogdet + sc2);
    }
}

// ---------------- main: per-point log-mixture, f32x2 packed FMAs, bulk-copy pipeline ----------------
__global__ void __launch_bounds__(128, 4) main_kernel(const float* __restrict__ X) {
    __shared__ KPack sP[2][2];                 // [ty][buf]
    __shared__ unsigned long long mbar[2][2];
    __shared__ float smx[2][64], ssm[2][64];
    int tx = threadIdx.x, ty = threadIdx.y;
    int tid = ty * 64 + tx;
    int n = blockIdx.x * 64 + tx;

    if (tid == 0) {
        for (int a = 0; a < 2; a++)
            for (int bq = 0; bq < 2; bq++) MBAR_INIT(smem_u32(&mbar[a][bq]), 1);
    }
    __syncthreads();

    // x packed into 32 f32x2 pairs
    unsigned long long xp[DD / 2];
    {
        const float4* xs = (const float4*)(X + (size_t)n * DD);
#pragma unroll
        for (int i = 0; i < 16; i++) {
            float4 v = xs[i];
            PK(xp[2 * i], v.x, v.y);
            PK(xp[2 * i + 1], v.z, v.w);
        }
    }

    int kbase = ty * 16;
    const unsigned KB = (unsigned)sizeof(KPack);
    // prologue: issue copies for i=0,1
    if (tx == 0) {
#pragma unroll
        for (int i = 0; i < 2; i++) {
            unsigned bar = smem_u32(&mbar[ty][i]);
            MBAR_EXPECT_TX(bar, KB);
            BULK_CP(smem_u32(&sP[ty][i]), &g_pk[kbase + i], KB, bar);
        }
    }

    float mx = -INFINITY, sm = 0.f;
#pragma unroll 1
    for (int i = 0; i < 16; i++) {
        int cur = i & 1;
        MBAR_WAIT(smem_u32(&mbar[ty][cur]), (i >> 1) & 1);

        const ulonglong2* Bp = sP[ty][cur].B;
        const unsigned long long* bp = sP[ty][cur].b;

        // b . x
        unsigned long long ba0 = 0ull, ba1 = 0ull;
#pragma unroll
        for (int s = 0; s < 32; s += 2) {
            FMA2(ba0, bp[s], xp[s]);
            FMA2(ba1, bp[s + 1], xp[s + 1]);
        }
        // quadratic: rows d=2s, 2s+1 (equal padded length)
        float acc0 = 0.f, acc1 = 0.f;
        int off = 0;
#pragma unroll
        for (int s = 0; s < 32; s++) {
            const int len = (s >> 1) + 1;       // ulonglong2 per row
            unsigned long long r0 = 0, r1 = 0, r2 = 0, r3 = 0;
#pragma unroll
            for (int p = 0; p < len; p++) {
                ulonglong2 v = Bp[off + p];
                FMA2(r0, v.x, xp[2 * p]);
                FMA2(r1, v.y, xp[2 * p + 1]);
            }
#pragma unroll
            for (int p = 0; p < len; p++) {
                ulonglong2 v = Bp[off + len + p];
                FMA2(r2, v.x, xp[2 * p]);
                FMA2(r3, v.y, xp[2 * p + 1]);
            }
            off += 2 * len;
            unsigned long long u0, u1;
            ADD2(u0, r0, r1);
            ADD2(u1, r2, r3);
            float l0, h0, l1, h1, xa, xb;
            UNPK(l0, h0, u0);
            UNPK(l1, h1, u1);
            UNPK(xa, xb, xp[s]);
            acc0 = fmaf(xa, l0 + h0, acc0);
            acc1 = fmaf(xb, l1 + h1, acc1);
        }
        unsigned long long bt;
        ADD2(bt, ba0, ba1);
        float bl, bh;
        UNPK(bl, bh, bt);
        float logp = sP[ty][cur].ck + bl + bh + acc0 + acc1;

        // online logsumexp over this thread's k
        if (logp > mx) {
            sm = fmaf(sm, expf(mx - logp), 1.0f);
            mx = logp;
        } else {
            sm += expf(logp - mx);
        }

        __syncthreads();    // all reads of buffer `cur` done
        if (i + 2 < 16 && tx == 0) {
            unsigned bar = smem_u32(&mbar[ty][cur]);
            MBAR_EXPECT_TX(bar, KB);
            BULK_CP(smem_u32(&sP[ty][cur]), &g_pk[kbase + i + 2], KB, bar);
        }
    }

    smx[ty][tx] = mx;
    ssm[ty][tx] = sm;
    __syncthreads();
    if (ty == 0) {
        float m0 = smx[0][tx], m1 = smx[1][tx];
        float s0 = ssm[0][tx], s1 = ssm[1][tx];
        float M = fmaxf(m0, m1);
        float S = s0 * expf(m0 - M) + s1 * expf(m1 - M);
        g_loglik[n] = M + logf(S);
    }
}

// ---------------- final reduce: -logsumexp over N ----------------
__global__ void reduce_kernel(float* __restrict__ out) {
    __shared__ float red[32];
    int tid = threadIdx.x;
    float m = -INFINITY;
    for (int i = tid; i < NPTS; i += 1024) m = fmaxf(m, g_loglik[i]);
    for (int o = 16; o; o >>= 1) m = fmaxf(m, __shfl_xor_sync(0xffffffffu, m, o));
    if ((tid & 31) == 0) red[tid >> 5] = m;
    __syncthreads();
    if (tid < 32) {
        float v = red[tid];
        for (int o = 16; o; o >>= 1) v = fmaxf(v, __shfl_xor_sync(0xffffffffu, v, o));
        if (tid == 0) red[0] = v;
    }
    __syncthreads();
    float M = red[0];
    __syncthreads();
    float s = 0.f;
    for (int i = tid; i < NPTS; i += 1024) s += expf(g_loglik[i] - M);
    for (int o = 16; o; o >>= 1) s += __shfl_xor_sync(0xffffffffu, s, o);
    if ((tid & 31) == 0) red[tid >> 5] = s;
    __syncthreads();
    if (tid == 0) {
        float t = 0.f;
        for (int i = 0; i < 32; i++) t += red[i];
        out[0] = -(M + logf(t));
    }
}

// ---------------- launch ----------------
extern "C" void kernel_launch(void* const* d_in, const int* in_sizes, int n_in,
                              void* d_out, int out_size) {
    const float* X  = (const float*)d_in[0];
    const float* mu = (const float*)d_in[1];
    const float* L  = (const float*)d_in[2];
    const float* w  = (const float*)d_in[3];
    float* out = (float*)d_out;

    setup_kernel<<<KK, 256>>>(L, mu, w);
    dim3 blk(64, 2);
    main_kernel<<<NPTS / 64, blk>>>(X);
    reduce_kernel<<<1, 1024>>>(out);
}

// round 5
// speedup vs baseline: 2.4678x; 1.2535x over previous
#include <cuda_runtime.h>
#include <math.h>

#define NPTS 32768
#define KK 32
#define DD 64
#define PACKED 2176                 // triangle rows padded to float4 boundaries (floats)
#define LOG_2PI 1.8378770664093453f

// ---------------- packed per-component parameter block ----------------
struct KPack {
    ulonglong2 B[PACKED / 4];       // 8704 B : -0.5*Sinv lower triangle (offdiag doubled)
    unsigned long long b[DD / 2];   // 256 B  : Sinv*mu as float pairs
    float ck;                       // logw - 0.5*(D log2pi + logdet + mu.b)
    float pad[3];                   // 8976 B total
};
__device__ KPack g_pk[KK];
__device__ float g_loglik[NPTS];
__device__ float g_rm[64], g_rs[64];

// ---------------- packed f32x2 helpers ----------------
#define FMA2(acc, a, b) asm("fma.rn.f32x2 %0, %1, %2, %0;" : "+l"(acc) : "l"(a), "l"(b))
#define ADD2(d, a, b)   asm("add.rn.f32x2 %0, %1, %2;" : "=l"(d) : "l"(a), "l"(b))
#define UNPK(lo, hi, v) asm("mov.b64 {%0, %1}, %2;" : "=f"(lo), "=f"(hi) : "l"(v))
#define PK(u, a, b)     asm("mov.b64 %0, {%1, %2};" : "=l"(u) : "f"(a), "f"(b))

// ---------------- mbarrier + bulk-copy helpers ----------------
__device__ __forceinline__ unsigned smem_u32(const void* p) {
    unsigned r;
    asm("{ .reg .u64 t; cvta.to.shared.u64 t, %1; cvt.u32.u64 %0, t; }" : "=r"(r) : "l"(p));
    return r;
}
#define MBAR_INIT(addr, cnt) \
    asm volatile("mbarrier.init.shared.b64 [%0], %1;" :: "r"(addr), "r"(cnt) : "memory")
#define MBAR_EXPECT_TX(addr, bytes) \
    asm volatile("mbarrier.arrive.expect_tx.shared.b64 _, [%0], %1;" :: "r"(addr), "r"(bytes) : "memory")
#define MBAR_WAIT(addr, parity) \
    asm volatile("{\n\t.reg .pred P;\n\tWL_%=:\n\t" \
        "mbarrier.try_wait.parity.acquire.cta.shared::cta.b64 P, [%0], %1, 0x989680;\n\t" \
        "@P bra.uni WD_%=;\n\tbra.uni WL_%=;\n\tWD_%=:\n\t}" \
        :: "r"(addr), "r"(parity) : "memory")
#define BULK_CP(dst, src, bytes, bar) \
    asm volatile("cp.async.bulk.shared::cluster.global.mbarrier::complete_tx::bytes [%0], [%1], %2, [%3];" \
        :: "r"(dst), "l"(src), "r"(bytes), "r"(bar) : "memory")

// ============= setup: Sigma -> Gauss-Jordan inverse -> pack (all-parallel) =============
extern __shared__ float dsm[];
__global__ void __launch_bounds__(512) setup_kernel(const float* __restrict__ L,
                                                    const float* __restrict__ mu,
                                                    const float* __restrict__ w) {
    float* Lt = dsm;                 // [64][65]  L transposed, padded
    float* M  = dsm + 64 * 65;       // [64][129] augmented [Sigma | I], padded
    __shared__ float colb[64];
    __shared__ float rowb[128];
    __shared__ float pivs[64];
    __shared__ float bsh[64];
    int k = blockIdx.x, tid = threadIdx.x;

    // load L transposed (conflict-free via 65 pad)
    for (int i = tid; i < DD * DD; i += 512) {
        int d = i >> 6, m = i & 63;
        Lt[m * 65 + d] = L[(size_t)k * DD * DD + i];
    }
    __syncthreads();

    // Sigma = tril(L) tril(L)^T + I into left half; identity into right half
    for (int i = tid; i < DD * DD; i += 512) {
        int d = i >> 6, e = i & 63;
        int mm = min(d, e);
        float s = (d == e) ? 1.0f : 0.0f;
        for (int m = 0; m <= mm; m++) s = fmaf(Lt[m * 65 + d], Lt[m * 65 + e], s);
        M[d * 129 + e] = s;
        M[d * 129 + 64 + e] = (d == e) ? 1.0f : 0.0f;
    }
    __syncthreads();

    // Gauss-Jordan (no pivoting: Sigma = I + LL^T is well-conditioned PD)
    for (int j = 0; j < DD; j++) {
        float piv = M[j * 129 + j];
        float inv = 1.0f / piv;
        if (tid < 64) colb[tid] = M[tid * 129 + j];
        if (tid < 128) rowb[tid] = M[j * 129 + tid] * inv;
        if (tid == 0) pivs[j] = piv;
        __syncthreads();
        for (int t = tid; t < DD * 128; t += 512) {
            int i = t >> 7, c = t & 127;
            float v = (i == j) ? rowb[c] : fmaf(-colb[i], rowb[c], M[i * 129 + c]);
            M[i * 129 + c] = v;
        }
        __syncthreads();
    }

    // pack B' rows from Sinv = M[.][64..127]
    {
        int d = tid >> 3, l8 = tid & 7;
        int q = d >> 2, r = d & 3;
        int off = 4 * (q + 1) * (2 * q + r);
        int plen = 4 * (q + 1);
        float* Bf = (float*)g_pk[k].B;
        const float* Sr = &M[d * 129 + 64];
        for (int e = l8; e < plen; e += 8) {
            float v = 0.f;
            if (e <= d) { float sv = Sr[e]; v = (e == d) ? -0.5f * sv : -sv; }
            Bf[off + e] = v;
        }
    }
    if (tid < 64) colb[tid] = mu[k * DD + tid];
    __syncthreads();

    // b = Sinv * mu (8 threads per row + shfl combine)
    {
        int d = tid >> 3, l8 = tid & 7;
        const float* Sr = &M[d * 129 + 64];
        float p = 0.f;
        for (int e = l8; e < DD; e += 8) p = fmaf(Sr[e], colb[e], p);
        p += __shfl_xor_sync(0xffffffffu, p, 1);
        p += __shfl_xor_sync(0xffffffffu, p, 2);
        p += __shfl_xor_sync(0xffffffffu, p, 4);
        if (l8 == 0) { bsh[d] = p; ((float*)g_pk[k].b)[d] = p; }
    }
    if (tid < 64) pivs[tid] = logf(pivs[tid]);
    __syncthreads();

    if (tid < 32) {
        float ldv = pivs[tid] + pivs[tid + 32];
        float c2 = bsh[tid] * colb[tid] + bsh[tid + 32] * colb[tid + 32];
        for (int o = 16; o; o >>= 1) {
            ldv += __shfl_xor_sync(0xffffffffu, ldv, o);
            c2  += __shfl_xor_sync(0xffffffffu, c2, o);
        }
        float wv = w[tid];
        float mxw = wv;
        for (int o = 16; o; o >>= 1) mxw = fmaxf(mxw, __shfl_xor_sync(0xffffffffu, mxw, o));
        float se = __expf(wv - mxw);
        for (int o = 16; o; o >>= 1) se += __shfl_xor_sync(0xffffffffu, se, o);
        float lgk = __shfl_sync(0xffffffffu, wv - (mxw + logf(se)), k);
        if (tid == 0) g_pk[k].ck = lgk - 0.5f * (DD * LOG_2PI + ldv + c2);
    }
}

// ============= main: 128 points/block, k processed in pairs, f32x2 FMAs =============
__global__ void __launch_bounds__(128, 3) main_kernel(const float* __restrict__ X) {
    __shared__ KPack sP[2][2];            // [buf][k-in-pair] : 35904 B
    __shared__ unsigned long long mbar[2];
    int tx = threadIdx.x;
    int n = blockIdx.x * 128 + tx;

    if (tx == 0) { MBAR_INIT(smem_u32(&mbar[0]), 1); MBAR_INIT(smem_u32(&mbar[1]), 1); }
    __syncthreads();

    // x packed into 32 f32x2 pairs
    unsigned long long xp[DD / 2];
    {
        const float4* xs = (const float4*)(X + (size_t)n * DD);
#pragma unroll
        for (int i = 0; i < 16; i++) {
            float4 v = xs[i];
            PK(xp[2 * i], v.x, v.y);
            PK(xp[2 * i + 1], v.z, v.w);
        }
    }

    const unsigned PB = 2u * (unsigned)sizeof(KPack);   // one k-pair
    if (tx == 0) {
#pragma unroll
        for (int bq = 0; bq < 2; bq++) {
            unsigned bar = smem_u32(&mbar[bq]);
            MBAR_EXPECT_TX(bar, PB);
            BULK_CP(smem_u32(&sP[bq][0]), &g_pk[2 * bq], PB, bar);
        }
    }

    float mx = -INFINITY, sm = 0.f;
#pragma unroll 1
    for (int p = 0; p < 16; p++) {
        int buf = p & 1;
        MBAR_WAIT(smem_u32(&mbar[buf]), (p >> 1) & 1);

        const ulonglong2* B0 = sP[buf][0].B;
        const ulonglong2* B1 = sP[buf][1].B;
        const unsigned long long* b0 = sP[buf][0].b;
        const unsigned long long* b1 = sP[buf][1].b;

        // b . x for both k
        unsigned long long e0 = 0ull, e1 = 0ull, f0 = 0ull, f1 = 0ull;
#pragma unroll
        for (int s = 0; s < 32; s += 2) {
            FMA2(e0, b0[s], xp[s]);     FMA2(e1, b0[s + 1], xp[s + 1]);
            FMA2(f0, b1[s], xp[s]);     FMA2(f1, b1[s + 1], xp[s + 1]);
        }

        float acc0 = 0.f, acc1 = 0.f, acc2 = 0.f, acc3 = 0.f;
        int off = 0;
#pragma unroll
        for (int s = 0; s < 32; s++) {
            const int len = (s >> 1) + 1;       // ulonglong2 per row
            unsigned long long r0 = 0, r1 = 0, r2 = 0, r3 = 0;
#pragma unroll
            for (int q = 0; q < len; q++) {
                ulonglong2 v0 = B0[off + q];
                ulonglong2 w0 = B0[off + len + q];
                ulonglong2 v1 = B1[off + q];
                ulonglong2 w1 = B1[off + len + q];
                FMA2(r0, v0.x, xp[2 * q]); FMA2(r0, v0.y, xp[2 * q + 1]);
                FMA2(r1, w0.x, xp[2 * q]); FMA2(r1, w0.y, xp[2 * q + 1]);
                FMA2(r2, v1.x, xp[2 * q]); FMA2(r2, v1.y, xp[2 * q + 1]);
                FMA2(r3, w1.x, xp[2 * q]); FMA2(r3, w1.y, xp[2 * q + 1]);
            }
            off += 2 * len;
            float xa, xb, la, ha, lb, hb, lc, hc, ld2, hd2;
            UNPK(xa, xb, xp[s]);
            UNPK(la, ha, r0); UNPK(lb, hb, r1);
            UNPK(lc, hc, r2); UNPK(ld2, hd2, r3);
            acc0 = fmaf(xa, la + ha, acc0);
            acc1 = fmaf(xb, lb + hb, acc1);
            acc2 = fmaf(xa, lc + hc, acc2);
            acc3 = fmaf(xb, ld2 + hd2, acc3);
        }
        unsigned long long t0, t1;
        ADD2(t0, e0, e1);
        ADD2(t1, f0, f1);
        float bl0, bh0, bl1, bh1;
        UNPK(bl0, bh0, t0);
        UNPK(bl1, bh1, t1);
        float logp0 = sP[buf][0].ck + bl0 + bh0 + acc0 + acc1;
        float logp1 = sP[buf][1].ck + bl1 + bh1 + acc2 + acc3;

        // online logsumexp (2 components)
        if (logp0 > mx) { sm = fmaf(sm, __expf(mx - logp0), 1.0f); mx = logp0; }
        else            { sm += __expf(logp0 - mx); }
        if (logp1 > mx) { sm = fmaf(sm, __expf(mx - logp1), 1.0f); mx = logp1; }
        else            { sm += __expf(logp1 - mx); }

        __syncthreads();    // all warps done reading buf
        if (p + 2 < 16 && tx == 0) {
            unsigned bar = smem_u32(&mbar[buf]);
            MBAR_EXPECT_TX(bar, PB);
            BULK_CP(smem_u32(&sP[buf][0]), &g_pk[2 * (p + 2)], PB, bar);
        }
    }
    g_loglik[n] = mx + logf(sm);
}

// ============= two-stage final reduce: -logsumexp over N =============
__global__ void reduceA_kernel() {
    __shared__ float red[8];
    int b = blockIdx.x, tid = threadIdx.x;
    const float* src = g_loglik + b * 512;
    float v0 = src[tid], v1 = src[tid + 256];
    float m = fmaxf(v0, v1);
    for (int o = 16; o; o >>= 1) m = fmaxf(m, __shfl_xor_sync(0xffffffffu, m, o));
    if ((tid & 31) == 0) red[tid >> 5] = m;
    __syncthreads();
    if (tid < 8) {
        float t = red[tid];
        for (int o = 4; o; o >>= 1) t = fmaxf(t, __shfl_xor_sync(0xffu, t, o));
        red[tid] = t;
    }
    __syncthreads();
    float M = red[0];
    float s = __expf(v0 - M) + __expf(v1 - M);
    for (int o = 16; o; o >>= 1) s += __shfl_xor_sync(0xffffffffu, s, o);
    __syncthreads();
    if ((tid & 31) == 0) red[tid >> 5] = s;
    __syncthreads();
    if (tid == 0) {
        float t = 0.f;
        for (int i = 0; i < 8; i++) t += red[i];
        g_rm[b] = M;
        g_rs[b] = t;
    }
}

__global__ void reduceB_kernel(float* __restrict__ out) {
    int lid = threadIdx.x;
    float m0 = g_rm[lid], m1 = g_rm[lid + 32];
    float m = fmaxf(m0, m1);
    for (int o = 16; o; o >>= 1) m = fmaxf(m, __shfl_xor_sync(0xffffffffu, m, o));
    float s = g_rs[lid] * __expf(m0 - m) + g_rs[lid + 32] * __expf(m1 - m);
    for (int o = 16; o; o >>= 1) s += __shfl_xor_sync(0xffffffffu, s, o);
    if (lid == 0) out[0] = -(m + logf(s));
}

// ---------------- launch ----------------
extern "C" void kernel_launch(void* const* d_in, const int* in_sizes, int n_in,
                              void* d_out, int out_size) {
    const float* X  = (const float*)d_in[0];
    const float* mu = (const float*)d_in[1];
    const float* L  = (const float*)d_in[2];
    const float* w  = (const float*)d_in[3];
    float* out = (float*)d_out;

    static int attr_done = 0;
    if (!attr_done) {
        cudaFuncSetAttribute(setup_kernel, cudaFuncAttributeMaxDynamicSharedMemorySize, 49664);
        attr_done = 1;
    }

    setup_kernel<<<KK, 512, 49664>>>(L, mu, w);
    main_kernel<<<NPTS / 128, 128>>>(X);
    reduceA_kernel<<<64, 256>>>();
    reduceB_kernel<<<1, 32>>>(out);
}